// round 2
// baseline (speedup 1.0000x reference)
#include <cuda_runtime.h>
#include <cuda_bf16.h>
#include <math.h>
#include <stdint.h>

// ---------------------------------------------------------------------------
// Problem constants
// ---------------------------------------------------------------------------
#define NIMG 2
#define NCH 256
#define A_ANCH 3
#define MALL 242991      // sum of H*W*A per image
#define MPOS 80997       // sum of H*W per image
#define MPROP 4741       // pooled proposals per image (1000*4 + 741)
#define POSTK 1000
#define NEG_INF (-1e9f)

__constant__ int c_H[5]      = {200, 100, 50, 25, 13};
__constant__ int c_W[5]      = {304, 152, 76, 38, 19};
__constant__ int c_stride[5] = {4, 8, 16, 32, 64};
__constant__ int c_size[5]   = {32, 64, 128, 256, 512};
__constant__ int c_hw[5]     = {60800, 15200, 3800, 950, 247};
__constant__ int c_hwa[5]    = {182400, 45600, 11400, 2850, 741};
__constant__ int c_abase[5]  = {0, 182400, 228000, 239400, 242250};
__constant__ int c_pbase[5]  = {0, 60800, 76000, 79800, 80750};
__constant__ int c_k[5]      = {1000, 1000, 1000, 1000, 741};
__constant__ int c_sbase[5]  = {0, 1000, 2000, 3000, 4000};

// ---------------------------------------------------------------------------
// Device scratch (static allocation - allowed)
// ---------------------------------------------------------------------------
__device__ float  g_wT[2304 * 256];                  // [ci*9+k][co]
__device__ float  g_t[(size_t)NIMG * MPOS * 256];    // [n*MPOS+pos][c]
__device__ float  g_logits[NIMG * MALL];
__device__ float  g_deltas[(size_t)NIMG * MALL * 4];
__device__ int    g_topk[10][1024];
__device__ int    g_eq[10][4096];
__device__ float4 g_pbox[NIMG][MPROP];
__device__ float  g_pscore[NIMG][MPROP];

// ---------------------------------------------------------------------------
// 0) weight transpose: conv_w [co][ci][ky][kx] -> g_wT [ci*9+k][co]
// ---------------------------------------------------------------------------
__global__ void transpose_w_kernel(const float* __restrict__ cw) {
    int row = blockIdx.x;     // 0..2303 = ci*9 + ky*3 + kx
    int co  = threadIdx.x;    // 0..255
    g_wT[row * 256 + co] = cw[co * 2304 + row];
}

// ---------------------------------------------------------------------------
// 1) Fused conv3x3 + bias + relu -> g_t[pos][c]
//    block 256 threads: pp = tid&7 (8 pos-groups of 8), cc = tid>>3 (32 ch-groups of 8)
//    tile = 64 positions in one row, all 256 output channels
// ---------------------------------------------------------------------------
#define CONV_SMEM ((72 * 256 + 8 * 3 * 68) * 4)

__global__ __launch_bounds__(256, 2)
void conv3x3_kernel(const float* __restrict__ feat, const float* __restrict__ cb,
                    int H, int W, int pB) {
    extern __shared__ float smem[];
    float* w_s  = smem;              // [72][256]
    float* in_s = smem + 72 * 256;   // [8][3][68]

    const int tid = threadIdx.x;
    const int pp  = tid & 7;
    const int cc  = tid >> 3;
    const int x0  = blockIdx.x * 64;
    const int y   = blockIdx.y;
    const int n   = blockIdx.z;

    float acc[8][8];
#pragma unroll
    for (int i = 0; i < 8; i++)
#pragma unroll
        for (int j = 0; j < 8; j++) acc[i][j] = 0.f;

    for (int ci0 = 0; ci0 < 256; ci0 += 8) {
        __syncthreads();
        // load weights (72 rows x 256, coalesced float4)
        {
            const float4* src = (const float4*)(g_wT + (size_t)ci0 * 9 * 256);
            float4* dst = (float4*)w_s;
#pragma unroll
            for (int k2 = 0; k2 < 18; k2++) dst[tid + k2 * 256] = src[tid + k2 * 256];
        }
        // load input tile: 8 ci x 3 rows x 66 cols (zero padded)
        for (int idx = tid; idx < 8 * 3 * 68; idx += 256) {
            int ciL = idx / 204;
            int rem = idx - ciL * 204;
            int r   = rem / 68;
            int xx  = rem - r * 68;
            float v = 0.f;
            if (xx < 66) {
                int gx = x0 - 1 + xx;
                int gy = y - 1 + r;
                if (gx >= 0 && gx < W && gy >= 0 && gy < H)
                    v = feat[((n * 256 + ci0 + ciL) * H + gy) * W + gx];
            }
            in_s[idx] = v;
        }
        __syncthreads();

#pragma unroll 1
        for (int ciL = 0; ciL < 8; ciL++) {
#pragma unroll
            for (int ky = 0; ky < 3; ky++) {
                float xr[10];
                const float* ip = &in_s[(ciL * 3 + ky) * 68 + pp * 8];
#pragma unroll
                for (int u = 0; u < 10; u++) xr[u] = ip[u];
#pragma unroll
                for (int kx = 0; kx < 3; kx++) {
                    const float* wrow = &w_s[((ciL * 3 + ky) * 3 + kx) * 256 + cc * 8];
                    float4 wa = *(const float4*)wrow;
                    float4 wb = *(const float4*)(wrow + 4);
                    float wr[8] = {wa.x, wa.y, wa.z, wa.w, wb.x, wb.y, wb.z, wb.w};
#pragma unroll
                    for (int i = 0; i < 8; i++)
#pragma unroll
                        for (int j = 0; j < 8; j++)
                            acc[i][j] = fmaf(xr[i + kx], wr[j], acc[i][j]);
                }
            }
        }
    }

    // epilogue: bias + relu, write t[pos][c]
    float cbv[8];
#pragma unroll
    for (int j = 0; j < 8; j++) cbv[j] = cb[cc * 8 + j];

    const int xbase = x0 + pp * 8;
#pragma unroll
    for (int i = 0; i < 8; i++) {
        int x = xbase + i;
        if (x < W) {
            size_t row = ((size_t)(n * MPOS + pB + y * W + x)) * 256 + cc * 8;
            float4 v0, v1;
            v0.x = fmaxf(acc[i][0] + cbv[0], 0.f);
            v0.y = fmaxf(acc[i][1] + cbv[1], 0.f);
            v0.z = fmaxf(acc[i][2] + cbv[2], 0.f);
            v0.w = fmaxf(acc[i][3] + cbv[3], 0.f);
            v1.x = fmaxf(acc[i][4] + cbv[4], 0.f);
            v1.y = fmaxf(acc[i][5] + cbv[5], 0.f);
            v1.z = fmaxf(acc[i][6] + cbv[6], 0.f);
            v1.w = fmaxf(acc[i][7] + cbv[7], 0.f);
            *(float4*)(g_t + row)     = v0;
            *(float4*)(g_t + row + 4) = v1;
        }
    }
}

// ---------------------------------------------------------------------------
// 2) 1x1 heads: logits (3) + deltas (12) per position
// ---------------------------------------------------------------------------
__global__ void head1x1_kernel(const float* __restrict__ ow, const float* __restrict__ ob,
                               const float* __restrict__ dw, const float* __restrict__ db,
                               int HW, int pB, int aB) {
    __shared__ float w2[15 * 256];
    __shared__ float b2[15];
    const int t = threadIdx.x;  // 128
    for (int i = t; i < 3 * 256; i += 128) w2[i] = ow[i];
    for (int i = t; i < 12 * 256; i += 128) w2[768 + i] = dw[i];
    if (t < 3) b2[t] = ob[t];
    else if (t < 15) b2[t] = db[t - 3];
    __syncthreads();

    int pos = blockIdx.x * 128 + t;
    int n   = blockIdx.y;
    if (pos >= HW) return;

    const float4* trow = (const float4*)(g_t + ((size_t)(n * MPOS + pB + pos)) * 256);
    float acc[15];
#pragma unroll
    for (int o = 0; o < 15; o++) acc[o] = 0.f;

#pragma unroll 4
    for (int c4 = 0; c4 < 64; c4++) {
        float4 tv = trow[c4];
#pragma unroll
        for (int o = 0; o < 15; o++) {
            const float* wr = &w2[o * 256 + c4 * 4];
            acc[o] += tv.x * wr[0] + tv.y * wr[1] + tv.z * wr[2] + tv.w * wr[3];
        }
    }
    size_t ob_ = (size_t)n * MALL;
    int m = aB + pos * 3;
#pragma unroll
    for (int a = 0; a < 3; a++) {
        g_logits[ob_ + m + a] = acc[a] + b2[a];
#pragma unroll
        for (int d = 0; d < 4; d++)
            g_deltas[(ob_ + m + a) * 4 + d] = acc[3 + a * 4 + d] + b2[3 + a * 4 + d];
    }
}

// ---------------------------------------------------------------------------
// 3) exact per-(image,level) top-k via 3-pass radix select + stable ties +
//    bitonic sort by (score desc, idx asc) to match lax.top_k ordering
// ---------------------------------------------------------------------------
__device__ __forceinline__ unsigned flipf(float f) {
    unsigned u = __float_as_uint(f);
    return (u & 0x80000000u) ? ~u : (u | 0x80000000u);
}

__global__ void topk_kernel() {
    const int blk = blockIdx.x;
    const int n = blk / 5, l = blk % 5;
    const int NE = c_hwa[l];
    const int K  = c_k[l];
    const float* sc = g_logits + (size_t)n * MALL + c_abase[l];

    __shared__ unsigned hist[2048];
    __shared__ unsigned long long sortbuf[1024];
    __shared__ unsigned sB1, sB2, sB3, sNeed, sCntGt, sCntEq;
    const int t = threadIdx.x;

    // ---- pass 1: top 11 bits ----
    for (int i = t; i < 2048; i += 256) hist[i] = 0;
    __syncthreads();
    for (int i = t; i < NE; i += 256) atomicAdd(&hist[flipf(sc[i]) >> 21], 1u);
    __syncthreads();
    if (t == 0) {
        unsigned acc = 0; int b = 2047;
        for (; b >= 0; b--) { unsigned h = hist[b]; if (acc + h >= (unsigned)K) break; acc += h; }
        sB1 = (unsigned)b; sNeed = (unsigned)K - acc;
    }
    __syncthreads();
    unsigned B1 = sB1, need1 = sNeed;

    // ---- pass 2: middle 11 bits ----
    for (int i = t; i < 2048; i += 256) hist[i] = 0;
    __syncthreads();
    for (int i = t; i < NE; i += 256) {
        unsigned k = flipf(sc[i]);
        if ((k >> 21) == B1) atomicAdd(&hist[(k >> 10) & 0x7FFu], 1u);
    }
    __syncthreads();
    if (t == 0) {
        unsigned acc = 0; int b = 2047;
        for (; b >= 0; b--) { unsigned h = hist[b]; if (acc + h >= need1) break; acc += h; }
        sB2 = (unsigned)b; sNeed = need1 - acc;
    }
    __syncthreads();
    unsigned B2 = sB2, need2 = sNeed;
    unsigned hi22 = (B1 << 11) | B2;

    // ---- pass 3: low 10 bits ----
    for (int i = t; i < 1024; i += 256) hist[i] = 0;
    __syncthreads();
    for (int i = t; i < NE; i += 256) {
        unsigned k = flipf(sc[i]);
        if ((k >> 10) == hi22) atomicAdd(&hist[k & 0x3FFu], 1u);
    }
    __syncthreads();
    if (t == 0) {
        unsigned acc = 0; int b = 1023;
        for (; b >= 0; b--) { unsigned h = hist[b]; if (acc + h >= need2) break; acc += h; }
        sB3 = (unsigned)b; sNeed = need2 - acc;
        sCntGt = 0; sCntEq = 0;
    }
    __syncthreads();
    unsigned T = (B1 << 21) | (B2 << 10) | sB3;
    unsigned need3 = sNeed;

    // ---- pass 4: collect ----
    for (int i = t; i < NE; i += 256) {
        unsigned k = flipf(sc[i]);
        if (k > T) {
            int s = (int)atomicAdd(&sCntGt, 1u);
            g_topk[blk][s] = i;
        } else if (k == T) {
            int e = (int)atomicAdd(&sCntEq, 1u);
            if (e < 4096) g_eq[blk][e] = i;
        }
    }
    __syncthreads();
    if (t == 0) {
        int base = (int)sCntGt;
        int rem  = K - base;   // == need3
        int ne   = (int)sCntEq; if (ne > 4096) ne = 4096;
        for (int r = 0; r < rem; r++) {
            int best = 0x7FFFFFFF, bj = -1;
            for (int j = 0; j < ne; j++)
                if (g_eq[blk][j] < best) { best = g_eq[blk][j]; bj = j; }
            if (bj >= 0) { g_topk[blk][base + r] = best; g_eq[blk][bj] = 0x7FFFFFFF; }
        }
        (void)need3;
    }
    __syncthreads();

    // ---- bitonic sort winners by (key desc, idx asc) ----
    for (int s = t; s < 1024; s += 256) {
        unsigned long long comb = 0ull;
        if (s < K) {
            int idx = g_topk[blk][s];
            comb = ((unsigned long long)flipf(sc[idx]) << 32) | (unsigned)(~(unsigned)idx);
        }
        sortbuf[s] = comb;
    }
    for (unsigned k2 = 2; k2 <= 1024; k2 <<= 1) {
        for (unsigned j = k2 >> 1; j > 0; j >>= 1) {
            __syncthreads();
            for (unsigned i = t; i < 1024; i += 256) {
                unsigned ixj = i ^ j;
                if (ixj > i) {
                    bool dir = ((i & k2) == 0);
                    unsigned long long a = sortbuf[i], b = sortbuf[ixj];
                    if ((a < b) == dir) { sortbuf[i] = b; sortbuf[ixj] = a; }
                }
            }
        }
    }
    __syncthreads();
    for (int s = t; s < K; s += 256)
        g_topk[blk][s] = (int)(~(unsigned)(sortbuf[s] & 0xFFFFFFFFull));
}

// ---------------------------------------------------------------------------
// 4) decode: anchor + apply_deltas + clip + validity
// ---------------------------------------------------------------------------
__global__ void decode_kernel() {
    int sid = blockIdx.x * 256 + threadIdx.x;
    if (sid >= NIMG * MPROP) return;
    int n = sid / MPROP, s = sid - n * MPROP;
    int l = s / 1000; if (l > 4) l = 4;
    int kl = s - c_sbase[l];
    int blk = n * 5 + l;
    int idx = g_topk[blk][kl];

    float score = g_logits[(size_t)n * MALL + c_abase[l] + idx];
    int pos = idx / 3, a = idx - pos * 3;
    int W = c_W[l];
    int yy = pos / W, xx = pos - yy * W;

    double size = (double)c_size[l];
    double ratio = (a == 0) ? 0.5 : ((a == 1) ? 1.0 : 2.0);
    double wd = sqrt(size * size / ratio);
    double hd = wd * ratio;
    float cax = (float)(-wd * 0.5);
    float cay = (float)(-hd * 0.5);
    float cax2 = (float)(wd * 0.5);
    float cay2 = (float)(hd * 0.5);

    float sx = (float)(xx * c_stride[l]);
    float sy = (float)(yy * c_stride[l]);
    float ax1 = sx + cax, ay1 = sy + cay, ax2 = sx + cax2, ay2 = sy + cay2;

    float w = ax2 - ax1, h = ay2 - ay1;
    float cx = ax1 + 0.5f * w, cy = ay1 + 0.5f * h;

    const float* dp = &g_deltas[((size_t)n * MALL + c_abase[l] + idx) * 4];
    float dxv = dp[0], dyv = dp[1];
    const float CLAMP = (float)4.135166556742356;
    float dwv = fminf(dp[2], CLAMP);
    float dhv = fminf(dp[3], CLAMP);

    float pcx = dxv * w + cx, pcy = dyv * h + cy;
    float pw = expf(dwv) * w, ph = expf(dhv) * h;

    float x1 = pcx - 0.5f * pw, y1 = pcy - 0.5f * ph;
    float x2 = pcx + 0.5f * pw, y2 = pcy + 0.5f * ph;
    x1 = fminf(fmaxf(x1, 0.f), 1216.f);
    x2 = fminf(fmaxf(x2, 0.f), 1216.f);
    y1 = fminf(fmaxf(y1, 0.f), 800.f);
    y2 = fminf(fmaxf(y2, 0.f), 800.f);

    bool valid = ((x2 - x1) > 0.f) && ((y2 - y1) > 0.f);
    g_pbox[n][s] = make_float4(x1, y1, x2, y2);
    g_pscore[n][s] = valid ? score : NEG_INF;
}

// ---------------------------------------------------------------------------
// 5) fixed-iteration greedy NMS in shared memory, one block per image
// ---------------------------------------------------------------------------
#define NMS_SMEM ((MPROP * 5 + 64) * 4)

__global__ __launch_bounds__(1024)
void nms_kernel(float* __restrict__ out) {
    extern __shared__ float sm[];
    float4* sbox = (float4*)sm;           // [MPROP]
    float*  ss   = sm + MPROP * 4;        // [MPROP]
    float*  rv   = ss + MPROP;            // [32]
    int*    ri   = (int*)(rv + 32);       // [32]
    __shared__ float s_bs;
    __shared__ int   s_bi;

    const int n = blockIdx.x;
    const int t = threadIdx.x;
    const int lane = t & 31, wid = t >> 5;

    for (int i = t; i < MPROP; i += 1024) {
        sbox[i] = g_pbox[n][i];
        ss[i]   = g_pscore[n][i];
    }
    __syncthreads();

    for (int it = 0; it < POSTK; it++) {
        // argmax with first-index tie-break (matches jnp.argmax)
        float bs = -3e38f; int bi = 0;
        for (int i = t; i < MPROP; i += 1024) {
            float s = ss[i];
            if (s > bs) { bs = s; bi = i; }
        }
#pragma unroll
        for (int o = 16; o > 0; o >>= 1) {
            float os = __shfl_down_sync(0xffffffffu, bs, o);
            int   oi = __shfl_down_sync(0xffffffffu, bi, o);
            if (os > bs || (os == bs && oi < bi)) { bs = os; bi = oi; }
        }
        if (lane == 0) { rv[wid] = bs; ri[wid] = bi; }
        __syncthreads();
        if (wid == 0) {
            bs = rv[lane]; bi = ri[lane];
#pragma unroll
            for (int o = 16; o > 0; o >>= 1) {
                float os = __shfl_down_sync(0xffffffffu, bs, o);
                int   oi = __shfl_down_sync(0xffffffffu, bi, o);
                if (os > bs || (os == bs && oi < bi)) { bs = os; bi = oi; }
            }
            if (lane == 0) { s_bs = bs; s_bi = bi; }
        }
        __syncthreads();

        const int bidx = s_bi;
        const float bscore = s_bs;
        const float4 bb = sbox[bidx];
        const float a1 = (bb.z - bb.x) * (bb.w - bb.y);

        for (int i = t; i < MPROP; i += 1024) {
            float4 c = sbox[i];
            float lx = fmaxf(bb.x, c.x), ly = fmaxf(bb.y, c.y);
            float rx = fminf(bb.z, c.z), ry = fminf(bb.w, c.w);
            float iw = fmaxf(rx - lx, 0.f), ih = fmaxf(ry - ly, 0.f);
            float inter = iw * ih;
            float a2 = (c.z - c.x) * (c.w - c.y);
            float iou = inter / fmaxf(a1 + a2 - inter, 1e-9f);
            if (iou > 0.7f) ss[i] = NEG_INF;
        }
        if (t == 0) {
            bool valid = bscore > (NEG_INF * 0.5f);
            float* o = out + ((size_t)n * POSTK + it) * 5;
            o[0] = valid ? bb.x : 0.f;
            o[1] = valid ? bb.y : 0.f;
            o[2] = valid ? bb.z : 0.f;
            o[3] = valid ? bb.w : 0.f;
            o[4] = valid ? bscore : NEG_INF;
        }
        __syncthreads();
    }
}

// ---------------------------------------------------------------------------
// launch
// ---------------------------------------------------------------------------
extern "C" void kernel_launch(void* const* d_in, const int* in_sizes, int n_in,
                              void* d_out, int out_size) {
    const float* feats[5];
    for (int i = 0; i < 5; i++) feats[i] = (const float*)d_in[i];
    const float* conv_w  = (const float*)d_in[5];
    const float* conv_b  = (const float*)d_in[6];
    const float* obj_w   = (const float*)d_in[7];
    const float* obj_b   = (const float*)d_in[8];
    const float* delta_w = (const float*)d_in[9];
    const float* delta_b = (const float*)d_in[10];
    float* out = (float*)d_out;

    static const int Hh[5] = {200, 100, 50, 25, 13};
    static const int Wh[5] = {304, 152, 76, 38, 19};
    static const int HWh[5] = {60800, 15200, 3800, 950, 247};
    static const int pBh[5] = {0, 60800, 76000, 79800, 80750};
    static const int aBh[5] = {0, 182400, 228000, 239400, 242250};

    cudaFuncSetAttribute(conv3x3_kernel, cudaFuncAttributeMaxDynamicSharedMemorySize, CONV_SMEM);
    cudaFuncSetAttribute(nms_kernel, cudaFuncAttributeMaxDynamicSharedMemorySize, NMS_SMEM);

    transpose_w_kernel<<<2304, 256>>>(conv_w);

    for (int l = 0; l < 5; l++) {
        dim3 grid((Wh[l] + 63) / 64, Hh[l], NIMG);
        conv3x3_kernel<<<grid, 256, CONV_SMEM>>>(feats[l], conv_b, Hh[l], Wh[l], pBh[l]);
    }
    for (int l = 0; l < 5; l++) {
        dim3 grid((HWh[l] + 127) / 128, NIMG);
        head1x1_kernel<<<grid, 128>>>(obj_w, obj_b, delta_w, delta_b, HWh[l], pBh[l], aBh[l]);
    }
    topk_kernel<<<10, 256>>>();
    decode_kernel<<<(NIMG * MPROP + 255) / 256, 256>>>();
    nms_kernel<<<NIMG, 1024, NMS_SMEM>>>(out);
}

// round 3
// speedup vs baseline: 1.2872x; 1.2872x over previous
#include <cuda_runtime.h>
#include <cuda_bf16.h>
#include <math.h>
#include <stdint.h>

// ---------------------------------------------------------------------------
// Problem constants
// ---------------------------------------------------------------------------
#define NIMG 2
#define NCH 256
#define A_ANCH 3
#define MALL 242991      // sum of H*W*A per image
#define MPOS 80997       // sum of H*W per image
#define MPROP 4741       // pooled proposals per image (1000*4 + 741)
#define POSTK 1000
#define NEG_INF (-1e9f)
#define NW 149           // ceil(MPROP/32)
#define NSORT 8192

__constant__ int c_H[5]      = {200, 100, 50, 25, 13};
__constant__ int c_W[5]      = {304, 152, 76, 38, 19};
__constant__ int c_stride[5] = {4, 8, 16, 32, 64};
__constant__ int c_size[5]   = {32, 64, 128, 256, 512};
__constant__ int c_hw[5]     = {60800, 15200, 3800, 950, 247};
__constant__ int c_hwa[5]    = {182400, 45600, 11400, 2850, 741};
__constant__ int c_abase[5]  = {0, 182400, 228000, 239400, 242250};
__constant__ int c_pbase[5]  = {0, 60800, 76000, 79800, 80750};
__constant__ int c_k[5]      = {1000, 1000, 1000, 1000, 741};
__constant__ int c_sbase[5]  = {0, 1000, 2000, 3000, 4000};

// ---------------------------------------------------------------------------
// Device scratch (static allocation - allowed)
// ---------------------------------------------------------------------------
__device__ float  g_wT[2304 * 256];                  // [ci*9+k][co]
__device__ float  g_t[(size_t)NIMG * MPOS * 256];    // [n*MPOS+pos][c]
__device__ float  g_logits[NIMG * MALL];
__device__ float  g_deltas[(size_t)NIMG * MALL * 4];
__device__ int    g_topk[10][1024];
__device__ int    g_eq[10][4096];
__device__ float4 g_pbox[NIMG][MPROP];
__device__ float  g_pscore[NIMG][MPROP];
__device__ float4 g_sbox[NIMG][MPROP];               // sorted boxes
__device__ float  g_sscore[NIMG][MPROP];             // sorted scores
__device__ unsigned g_mask[NIMG][MPROP][NW];         // suppression bitmask

// ---------------------------------------------------------------------------
// 0) weight transpose: conv_w [co][ci][ky][kx] -> g_wT [ci*9+k][co]
// ---------------------------------------------------------------------------
__global__ void transpose_w_kernel(const float* __restrict__ cw) {
    int row = blockIdx.x;     // 0..2303 = ci*9 + ky*3 + kx
    int co  = threadIdx.x;    // 0..255
    g_wT[row * 256 + co] = cw[co * 2304 + row];
}

// ---------------------------------------------------------------------------
// 1) Fused conv3x3 + bias + relu -> g_t[pos][c]
// ---------------------------------------------------------------------------
#define CONV_SMEM ((72 * 256 + 8 * 3 * 68) * 4)

__global__ __launch_bounds__(256, 2)
void conv3x3_kernel(const float* __restrict__ feat, const float* __restrict__ cb,
                    int H, int W, int pB) {
    extern __shared__ float smem[];
    float* w_s  = smem;              // [72][256]
    float* in_s = smem + 72 * 256;   // [8][3][68]

    const int tid = threadIdx.x;
    const int pp  = tid & 7;
    const int cc  = tid >> 3;
    const int x0  = blockIdx.x * 64;
    const int y   = blockIdx.y;
    const int n   = blockIdx.z;

    float acc[8][8];
#pragma unroll
    for (int i = 0; i < 8; i++)
#pragma unroll
        for (int j = 0; j < 8; j++) acc[i][j] = 0.f;

    for (int ci0 = 0; ci0 < 256; ci0 += 8) {
        __syncthreads();
        {
            const float4* src = (const float4*)(g_wT + (size_t)ci0 * 9 * 256);
            float4* dst = (float4*)w_s;
#pragma unroll
            for (int k2 = 0; k2 < 18; k2++) dst[tid + k2 * 256] = src[tid + k2 * 256];
        }
        for (int idx = tid; idx < 8 * 3 * 68; idx += 256) {
            int ciL = idx / 204;
            int rem = idx - ciL * 204;
            int r   = rem / 68;
            int xx  = rem - r * 68;
            float v = 0.f;
            if (xx < 66) {
                int gx = x0 - 1 + xx;
                int gy = y - 1 + r;
                if (gx >= 0 && gx < W && gy >= 0 && gy < H)
                    v = feat[((n * 256 + ci0 + ciL) * H + gy) * W + gx];
            }
            in_s[idx] = v;
        }
        __syncthreads();

#pragma unroll 1
        for (int ciL = 0; ciL < 8; ciL++) {
#pragma unroll
            for (int ky = 0; ky < 3; ky++) {
                float xr[10];
                const float* ip = &in_s[(ciL * 3 + ky) * 68 + pp * 8];
#pragma unroll
                for (int u = 0; u < 10; u++) xr[u] = ip[u];
#pragma unroll
                for (int kx = 0; kx < 3; kx++) {
                    const float* wrow = &w_s[((ciL * 3 + ky) * 3 + kx) * 256 + cc * 8];
                    float4 wa = *(const float4*)wrow;
                    float4 wb = *(const float4*)(wrow + 4);
                    float wr[8] = {wa.x, wa.y, wa.z, wa.w, wb.x, wb.y, wb.z, wb.w};
#pragma unroll
                    for (int i = 0; i < 8; i++)
#pragma unroll
                        for (int j = 0; j < 8; j++)
                            acc[i][j] = fmaf(xr[i + kx], wr[j], acc[i][j]);
                }
            }
        }
    }

    float cbv[8];
#pragma unroll
    for (int j = 0; j < 8; j++) cbv[j] = cb[cc * 8 + j];

    const int xbase = x0 + pp * 8;
#pragma unroll
    for (int i = 0; i < 8; i++) {
        int x = xbase + i;
        if (x < W) {
            size_t row = ((size_t)(n * MPOS + pB + y * W + x)) * 256 + cc * 8;
            float4 v0, v1;
            v0.x = fmaxf(acc[i][0] + cbv[0], 0.f);
            v0.y = fmaxf(acc[i][1] + cbv[1], 0.f);
            v0.z = fmaxf(acc[i][2] + cbv[2], 0.f);
            v0.w = fmaxf(acc[i][3] + cbv[3], 0.f);
            v1.x = fmaxf(acc[i][4] + cbv[4], 0.f);
            v1.y = fmaxf(acc[i][5] + cbv[5], 0.f);
            v1.z = fmaxf(acc[i][6] + cbv[6], 0.f);
            v1.w = fmaxf(acc[i][7] + cbv[7], 0.f);
            *(float4*)(g_t + row)     = v0;
            *(float4*)(g_t + row + 4) = v1;
        }
    }
}

// ---------------------------------------------------------------------------
// 2) 1x1 heads: logits (3) + deltas (12) per position
// ---------------------------------------------------------------------------
__global__ void head1x1_kernel(const float* __restrict__ ow, const float* __restrict__ ob,
                               const float* __restrict__ dw, const float* __restrict__ db,
                               int HW, int pB, int aB) {
    __shared__ float w2[15 * 256];
    __shared__ float b2[15];
    const int t = threadIdx.x;  // 128
    for (int i = t; i < 3 * 256; i += 128) w2[i] = ow[i];
    for (int i = t; i < 12 * 256; i += 128) w2[768 + i] = dw[i];
    if (t < 3) b2[t] = ob[t];
    else if (t < 15) b2[t] = db[t - 3];
    __syncthreads();

    int pos = blockIdx.x * 128 + t;
    int n   = blockIdx.y;
    if (pos >= HW) return;

    const float4* trow = (const float4*)(g_t + ((size_t)(n * MPOS + pB + pos)) * 256);
    float acc[15];
#pragma unroll
    for (int o = 0; o < 15; o++) acc[o] = 0.f;

#pragma unroll 4
    for (int c4 = 0; c4 < 64; c4++) {
        float4 tv = trow[c4];
#pragma unroll
        for (int o = 0; o < 15; o++) {
            const float* wr = &w2[o * 256 + c4 * 4];
            acc[o] += tv.x * wr[0] + tv.y * wr[1] + tv.z * wr[2] + tv.w * wr[3];
        }
    }
    size_t ob_ = (size_t)n * MALL;
    int m = aB + pos * 3;
#pragma unroll
    for (int a = 0; a < 3; a++) {
        g_logits[ob_ + m + a] = acc[a] + b2[a];
#pragma unroll
        for (int d = 0; d < 4; d++)
            g_deltas[(ob_ + m + a) * 4 + d] = acc[3 + a * 4 + d] + b2[3 + a * 4 + d];
    }
}

// ---------------------------------------------------------------------------
// 3) exact per-(image,level) top-k via 3-pass radix select + stable ties +
//    bitonic sort by (score desc, idx asc) to match lax.top_k ordering
// ---------------------------------------------------------------------------
__device__ __forceinline__ unsigned flipf(float f) {
    unsigned u = __float_as_uint(f);
    return (u & 0x80000000u) ? ~u : (u | 0x80000000u);
}

__global__ void topk_kernel() {
    const int blk = blockIdx.x;
    const int n = blk / 5, l = blk % 5;
    const int NE = c_hwa[l];
    const int K  = c_k[l];
    const float* sc = g_logits + (size_t)n * MALL + c_abase[l];

    __shared__ unsigned hist[2048];
    __shared__ unsigned long long sortbuf[1024];
    __shared__ unsigned sB1, sB2, sB3, sNeed, sCntGt, sCntEq;
    const int t = threadIdx.x;

    for (int i = t; i < 2048; i += 256) hist[i] = 0;
    __syncthreads();
    for (int i = t; i < NE; i += 256) atomicAdd(&hist[flipf(sc[i]) >> 21], 1u);
    __syncthreads();
    if (t == 0) {
        unsigned acc = 0; int b = 2047;
        for (; b >= 0; b--) { unsigned h = hist[b]; if (acc + h >= (unsigned)K) break; acc += h; }
        sB1 = (unsigned)b; sNeed = (unsigned)K - acc;
    }
    __syncthreads();
    unsigned B1 = sB1, need1 = sNeed;

    for (int i = t; i < 2048; i += 256) hist[i] = 0;
    __syncthreads();
    for (int i = t; i < NE; i += 256) {
        unsigned k = flipf(sc[i]);
        if ((k >> 21) == B1) atomicAdd(&hist[(k >> 10) & 0x7FFu], 1u);
    }
    __syncthreads();
    if (t == 0) {
        unsigned acc = 0; int b = 2047;
        for (; b >= 0; b--) { unsigned h = hist[b]; if (acc + h >= need1) break; acc += h; }
        sB2 = (unsigned)b; sNeed = need1 - acc;
    }
    __syncthreads();
    unsigned B2 = sB2, need2 = sNeed;
    unsigned hi22 = (B1 << 11) | B2;

    for (int i = t; i < 1024; i += 256) hist[i] = 0;
    __syncthreads();
    for (int i = t; i < NE; i += 256) {
        unsigned k = flipf(sc[i]);
        if ((k >> 10) == hi22) atomicAdd(&hist[k & 0x3FFu], 1u);
    }
    __syncthreads();
    if (t == 0) {
        unsigned acc = 0; int b = 1023;
        for (; b >= 0; b--) { unsigned h = hist[b]; if (acc + h >= need2) break; acc += h; }
        sB3 = (unsigned)b; sNeed = need2 - acc;
        sCntGt = 0; sCntEq = 0;
    }
    __syncthreads();
    unsigned T = (B1 << 21) | (B2 << 10) | sB3;

    for (int i = t; i < NE; i += 256) {
        unsigned k = flipf(sc[i]);
        if (k > T) {
            int s = (int)atomicAdd(&sCntGt, 1u);
            g_topk[blk][s] = i;
        } else if (k == T) {
            int e = (int)atomicAdd(&sCntEq, 1u);
            if (e < 4096) g_eq[blk][e] = i;
        }
    }
    __syncthreads();
    if (t == 0) {
        int base = (int)sCntGt;
        int rem  = K - base;
        int ne   = (int)sCntEq; if (ne > 4096) ne = 4096;
        for (int r = 0; r < rem; r++) {
            int best = 0x7FFFFFFF, bj = -1;
            for (int j = 0; j < ne; j++)
                if (g_eq[blk][j] < best) { best = g_eq[blk][j]; bj = j; }
            if (bj >= 0) { g_topk[blk][base + r] = best; g_eq[blk][bj] = 0x7FFFFFFF; }
        }
    }
    __syncthreads();

    for (int s = t; s < 1024; s += 256) {
        unsigned long long comb = 0ull;
        if (s < K) {
            int idx = g_topk[blk][s];
            comb = ((unsigned long long)flipf(sc[idx]) << 32) | (unsigned)(~(unsigned)idx);
        }
        sortbuf[s] = comb;
    }
    for (unsigned k2 = 2; k2 <= 1024; k2 <<= 1) {
        for (unsigned j = k2 >> 1; j > 0; j >>= 1) {
            __syncthreads();
            for (unsigned i = t; i < 1024; i += 256) {
                unsigned ixj = i ^ j;
                if (ixj > i) {
                    bool dir = ((i & k2) == 0);
                    unsigned long long a = sortbuf[i], b = sortbuf[ixj];
                    if ((a < b) == dir) { sortbuf[i] = b; sortbuf[ixj] = a; }
                }
            }
        }
    }
    __syncthreads();
    for (int s = t; s < K; s += 256)
        g_topk[blk][s] = (int)(~(unsigned)(sortbuf[s] & 0xFFFFFFFFull));
}

// ---------------------------------------------------------------------------
// 4) decode: anchor + apply_deltas + clip + validity
// ---------------------------------------------------------------------------
__global__ void decode_kernel() {
    int sid = blockIdx.x * 256 + threadIdx.x;
    if (sid >= NIMG * MPROP) return;
    int n = sid / MPROP, s = sid - n * MPROP;
    int l = s / 1000; if (l > 4) l = 4;
    int kl = s - c_sbase[l];
    int blk = n * 5 + l;
    int idx = g_topk[blk][kl];

    float score = g_logits[(size_t)n * MALL + c_abase[l] + idx];
    int pos = idx / 3, a = idx - pos * 3;
    int W = c_W[l];
    int yy = pos / W, xx = pos - yy * W;

    double size = (double)c_size[l];
    double ratio = (a == 0) ? 0.5 : ((a == 1) ? 1.0 : 2.0);
    double wd = sqrt(size * size / ratio);
    double hd = wd * ratio;
    float cax = (float)(-wd * 0.5);
    float cay = (float)(-hd * 0.5);
    float cax2 = (float)(wd * 0.5);
    float cay2 = (float)(hd * 0.5);

    float sx = (float)(xx * c_stride[l]);
    float sy = (float)(yy * c_stride[l]);
    float ax1 = sx + cax, ay1 = sy + cay, ax2 = sx + cax2, ay2 = sy + cay2;

    float w = ax2 - ax1, h = ay2 - ay1;
    float cx = ax1 + 0.5f * w, cy = ay1 + 0.5f * h;

    const float* dp = &g_deltas[((size_t)n * MALL + c_abase[l] + idx) * 4];
    float dxv = dp[0], dyv = dp[1];
    const float CLAMP = (float)4.135166556742356;
    float dwv = fminf(dp[2], CLAMP);
    float dhv = fminf(dp[3], CLAMP);

    float pcx = dxv * w + cx, pcy = dyv * h + cy;
    float pw = expf(dwv) * w, ph = expf(dhv) * h;

    float x1 = pcx - 0.5f * pw, y1 = pcy - 0.5f * ph;
    float x2 = pcx + 0.5f * pw, y2 = pcy + 0.5f * ph;
    x1 = fminf(fmaxf(x1, 0.f), 1216.f);
    x2 = fminf(fmaxf(x2, 0.f), 1216.f);
    y1 = fminf(fmaxf(y1, 0.f), 800.f);
    y2 = fminf(fmaxf(y2, 0.f), 800.f);

    bool valid = ((x2 - x1) > 0.f) && ((y2 - y1) > 0.f);
    g_pbox[n][s] = make_float4(x1, y1, x2, y2);
    g_pscore[n][s] = valid ? score : NEG_INF;
}

// ---------------------------------------------------------------------------
// 5a) global sort of pooled proposals by (score desc, idx asc)
// ---------------------------------------------------------------------------
__global__ __launch_bounds__(1024)
void sort_kernel() {
    extern __shared__ unsigned long long sb[];
    const int n = blockIdx.x;
    const int t = threadIdx.x;

    for (int i = t; i < NSORT; i += 1024) {
        unsigned long long key = 0ull;
        if (i < MPROP) {
            float s = g_pscore[n][i];
            key = ((unsigned long long)flipf(s) << 32) | (unsigned)(~(unsigned)i);
        }
        sb[i] = key;
    }
    for (unsigned k2 = 2; k2 <= NSORT; k2 <<= 1) {
        for (unsigned j = k2 >> 1; j > 0; j >>= 1) {
            __syncthreads();
            for (unsigned i = t; i < NSORT; i += 1024) {
                unsigned ixj = i ^ j;
                if (ixj > i) {
                    bool dir = ((i & k2) == 0);
                    unsigned long long a = sb[i], b = sb[ixj];
                    if ((a < b) == dir) { sb[i] = b; sb[ixj] = a; }
                }
            }
        }
    }
    __syncthreads();
    for (int r = t; r < MPROP; r += 1024) {
        unsigned idx = ~(unsigned)(sb[r] & 0xFFFFFFFFull);
        g_sbox[n][r]   = g_pbox[n][idx];
        g_sscore[n][r] = g_pscore[n][idx];
    }
}

// ---------------------------------------------------------------------------
// 5b) pairwise suppression bitmask: bit j of g_mask[n][i][w] = IoU(i, w*32+j)>0.7
// ---------------------------------------------------------------------------
__global__ __launch_bounds__(512)
void mask_kernel() {
    __shared__ float4 jb[128];
    const int n = blockIdx.z;
    const int tid = threadIdx.x;
    const int i = blockIdx.x * 128 + (tid & 127);
    const int wloc = tid >> 7;              // 0..3
    const int w = blockIdx.y * 4 + wloc;
    const int j0 = blockIdx.y * 128;

    if (tid < 128) {
        int j = j0 + tid;
        jb[tid] = (j < MPROP) ? g_sbox[n][j] : make_float4(0.f, 0.f, 0.f, 0.f);
    }
    __syncthreads();
    if (i >= MPROP || w >= NW) return;

    float4 b = g_sbox[n][i];
    float a1 = (b.z - b.x) * (b.w - b.y);
    unsigned bits = 0u;
#pragma unroll
    for (int jj = 0; jj < 32; jj++) {
        int j = w * 32 + jj;
        if (j < MPROP) {
            float4 c = jb[wloc * 32 + jj];
            float lx = fmaxf(b.x, c.x), ly = fmaxf(b.y, c.y);
            float rx = fminf(b.z, c.z), ry = fminf(b.w, c.w);
            float iw = fmaxf(rx - lx, 0.f), ih = fmaxf(ry - ly, 0.f);
            float inter = iw * ih;
            float a2 = (c.z - c.x) * (c.w - c.y);
            float iou = inter / fmaxf(a1 + a2 - inter, 1e-9f);
            if (iou > 0.7f) bits |= (1u << jj);
        }
    }
    g_mask[n][i][w] = bits;
}

// ---------------------------------------------------------------------------
// 5c) sequential scan over sorted order with bitmask suppression
// ---------------------------------------------------------------------------
__global__ __launch_bounds__(192)
void scan_kernel(float* __restrict__ out) {
    __shared__ unsigned removed[NW];
    __shared__ float ssc[MPROP];
    const int n = blockIdx.x;
    const int t = threadIdx.x;

    for (int w = t; w < NW; w += 192) removed[w] = 0u;
    for (int i = t; i < MPROP; i += 192) ssc[i] = g_sscore[n][i];
    __syncthreads();

    int k = 0;
    for (int i = 0; i < MPROP; i++) {
        float sc = ssc[i];
        if (!(sc > -5e8f)) break;               // sorted: all remaining invalid
        unsigned bit = (removed[i >> 5] >> (i & 31)) & 1u;
        if (!bit) {
            if (t == 0) {
                float4 b = g_sbox[n][i];
                float* o = out + ((size_t)n * POSTK + k) * 5;
                o[0] = b.x; o[1] = b.y; o[2] = b.z; o[3] = b.w; o[4] = sc;
            }
            const unsigned* mrow = g_mask[n][i];
            for (int w = t; w < NW; w += 192) removed[w] |= mrow[w];
            __syncthreads();
            k++;
            if (k == POSTK) break;
        }
    }
    // pad remaining rows
    for (int r = k + t; r < POSTK; r += 192) {
        float* o = out + ((size_t)n * POSTK + r) * 5;
        o[0] = 0.f; o[1] = 0.f; o[2] = 0.f; o[3] = 0.f; o[4] = NEG_INF;
    }
}

// ---------------------------------------------------------------------------
// launch
// ---------------------------------------------------------------------------
extern "C" void kernel_launch(void* const* d_in, const int* in_sizes, int n_in,
                              void* d_out, int out_size) {
    const float* feats[5];
    for (int i = 0; i < 5; i++) feats[i] = (const float*)d_in[i];
    const float* conv_w  = (const float*)d_in[5];
    const float* conv_b  = (const float*)d_in[6];
    const float* obj_w   = (const float*)d_in[7];
    const float* obj_b   = (const float*)d_in[8];
    const float* delta_w = (const float*)d_in[9];
    const float* delta_b = (const float*)d_in[10];
    float* out = (float*)d_out;

    static const int Hh[5] = {200, 100, 50, 25, 13};
    static const int Wh[5] = {304, 152, 76, 38, 19};
    static const int HWh[5] = {60800, 15200, 3800, 950, 247};
    static const int pBh[5] = {0, 60800, 76000, 79800, 80750};
    static const int aBh[5] = {0, 182400, 228000, 239400, 242250};

    cudaFuncSetAttribute(conv3x3_kernel, cudaFuncAttributeMaxDynamicSharedMemorySize, CONV_SMEM);
    cudaFuncSetAttribute(sort_kernel, cudaFuncAttributeMaxDynamicSharedMemorySize, NSORT * 8);

    transpose_w_kernel<<<2304, 256>>>(conv_w);

    for (int l = 0; l < 5; l++) {
        dim3 grid((Wh[l] + 63) / 64, Hh[l], NIMG);
        conv3x3_kernel<<<grid, 256, CONV_SMEM>>>(feats[l], conv_b, Hh[l], Wh[l], pBh[l]);
    }
    for (int l = 0; l < 5; l++) {
        dim3 grid((HWh[l] + 127) / 128, NIMG);
        head1x1_kernel<<<grid, 128>>>(obj_w, obj_b, delta_w, delta_b, HWh[l], pBh[l], aBh[l]);
    }
    topk_kernel<<<10, 256>>>();
    decode_kernel<<<(NIMG * MPROP + 255) / 256, 256>>>();

    sort_kernel<<<NIMG, 1024, NSORT * 8>>>();
    {
        dim3 grid((MPROP + 127) / 128, (NW + 3) / 4, NIMG);
        mask_kernel<<<grid, 512>>>();
    }
    scan_kernel<<<NIMG, 192>>>(out);
}